// round 1
// baseline (speedup 1.0000x reference)
#include <cuda_runtime.h>
#include <math.h>

#define CAP_E 655360
#define CAP_N 20004

// Scratch (allocation-free rule: __device__ globals)
__device__ float g_logits[CAP_E];
__device__ float g_ex[CAP_E];
__device__ int   g_starts[CAP_N];

typedef unsigned long long ull;

__device__ __forceinline__ ull fma2(ull a, ull b, ull c) {
    ull d;
    asm("fma.rn.f32x2 %0, %1, %2, %3;" : "=l"(d) : "l"(a), "l"(b), "l"(c));
    return d;
}
__device__ __forceinline__ ull pack2(float lo, float hi) {
    ull r;
    asm("mov.b64 %0, {%1, %2};" : "=l"(r) : "f"(lo), "f"(hi));
    return r;
}
__device__ __forceinline__ float2 unpack2(ull v) {
    float2 r;
    asm("mov.b64 {%0, %1}, %2;" : "=f"(r.x), "=f"(r.y) : "l"(v));
    return r;
}

// ---------------------------------------------------------------------------
// Kernel 1: per-node edge-range starts via binary search on sorted seg_ids
// ---------------------------------------------------------------------------
__global__ void starts_kernel(const int* __restrict__ seg, int E, int N) {
    int n = blockIdx.x * blockDim.x + threadIdx.x;
    if (n > N) return;
    if (n == N) { g_starts[N] = E; return; }
    int lo = 0, hi = E;
    while (lo < hi) {
        int mid = (lo + hi) >> 1;
        if (seg[mid] < n) lo = mid + 1; else hi = mid;
    }
    g_starts[n] = lo;
}

// ---------------------------------------------------------------------------
// Kernel 2: per-edge MLP -> logit. One thread per edge.
// Shared: W1 pair-packed [128][32] ull (32KB), W2^T pair-packed [64][32] ull
// (16KB), b2[64], w3[64]. All weight reads are warp-uniform -> LDS broadcast.
// Math in packed f32x2 (FFMA2) to double FMA-pipe throughput.
// ---------------------------------------------------------------------------
__global__ __launch_bounds__(128, 4) void mlp_kernel(
    const int* __restrict__ nodes, const int* __restrict__ neigh,
    const int* __restrict__ seg, const float* __restrict__ u2e,
    const float* __restrict__ w1, const float* __restrict__ b1,
    const float* __restrict__ w2, const float* __restrict__ b2,
    const float* __restrict__ w3, const float* __restrict__ b3,
    int E)
{
    extern __shared__ char smem[];
    ull*   s_w1 = (ull*)smem;                   // 4096 ull = 32768 B
    ull*   s_w2 = (ull*)(smem + 32768);         // 2048 ull = 16384 B
    float* s_b2 = (float*)(smem + 49152);       // 256 B
    float* s_w3 = (float*)(smem + 49408);       // 256 B
    const int tid = threadIdx.x;

    // W1 is [128][64] row-major; adjacent j pairs are contiguous -> raw copy.
    const ull* w1p = (const ull*)w1;
    for (int i = tid; i < 4096; i += 128) s_w1[i] = w1p[i];
    // W2 transposed + packed over k-pairs: s_w2[j2*32 + kp] = {W2[2kp][j2], W2[2kp+1][j2]}
    for (int i = tid; i < 2048; i += 128) {
        int j2 = i >> 5, kp = i & 31;
        s_w2[i] = pack2(w2[(2 * kp) * 64 + j2], w2[(2 * kp + 1) * 64 + j2]);
    }
    if (tid < 64) { s_b2[tid] = b2[tid]; s_w3[tid] = w3[tid]; }
    __syncthreads();

    int e = blockIdx.x * 128 + tid;
    if (e >= E) return;

    const int nb  = neigh[e];
    const int sg  = seg[e];
    const int ctr = nodes[sg];

    // acc[jp] holds h1 outputs (j=2jp, 2jp+1), init with bias b1 (packed pairs)
    ull acc[32];
    const ull* b1p = (const ull*)b1;
    #pragma unroll
    for (int jp = 0; jp < 32; jp++) acc[jp] = b1p[jp];

    const float4* eu4 = (const float4*)(u2e + (size_t)nb  * 64);
    const float4* ur4 = (const float4*)(u2e + (size_t)ctr * 64);

    // Layer 1, first half: x[k] = e_u[k], k = 0..63
    #pragma unroll 1
    for (int c = 0; c < 16; c++) {
        float4 xv = eu4[c];
        float xs[4] = {xv.x, xv.y, xv.z, xv.w};
        #pragma unroll
        for (int kk = 0; kk < 4; kk++) {
            ull xx = pack2(xs[kk], xs[kk]);
            const ull* wr = &s_w1[(c * 4 + kk) * 32];
            #pragma unroll
            for (int jp = 0; jp < 32; jp += 2) {
                ulonglong2 w = *(const ulonglong2*)&wr[jp];
                acc[jp]     = fma2(xx, w.x, acc[jp]);
                acc[jp + 1] = fma2(xx, w.y, acc[jp + 1]);
            }
        }
    }
    // Layer 1, second half: x[64+k] = u_rep[k]
    #pragma unroll 1
    for (int c = 0; c < 16; c++) {
        float4 xv = ur4[c];
        float xs[4] = {xv.x, xv.y, xv.z, xv.w};
        #pragma unroll
        for (int kk = 0; kk < 4; kk++) {
            ull xx = pack2(xs[kk], xs[kk]);
            const ull* wr = &s_w1[(64 + c * 4 + kk) * 32];
            #pragma unroll
            for (int jp = 0; jp < 32; jp += 2) {
                ulonglong2 w = *(const ulonglong2*)&wr[jp];
                acc[jp]     = fma2(xx, w.x, acc[jp]);
                acc[jp + 1] = fma2(xx, w.y, acc[jp + 1]);
            }
        }
    }
    // ReLU h1
    #pragma unroll
    for (int jp = 0; jp < 32; jp++) {
        float2 v = unpack2(acc[jp]);
        acc[jp] = pack2(fmaxf(v.x, 0.0f), fmaxf(v.y, 0.0f));
    }

    // Layer 2 + Layer 3 fused: logit = b3 + sum_j2 relu(b2[j2] + h1 . W2[:,j2]) * w3[j2]
    float logit = b3[0];
    #pragma unroll 1
    for (int j2 = 0; j2 < 64; j2++) {
        ull t0 = 0ull, t1 = 0ull;  // packed zeros
        const ull* wr = &s_w2[j2 * 32];
        #pragma unroll
        for (int kp = 0; kp < 32; kp += 2) {
            ulonglong2 w = *(const ulonglong2*)&wr[kp];
            t0 = fma2(acc[kp],     w.x, t0);
            t1 = fma2(acc[kp + 1], w.y, t1);
        }
        float2 u0 = unpack2(t0), u1 = unpack2(t1);
        float t = (u0.x + u0.y) + (u1.x + u1.y) + s_b2[j2];
        t = fmaxf(t, 0.0f);
        logit = fmaf(t, s_w3[j2], logit);
    }
    g_logits[e] = logit;
}

// ---------------------------------------------------------------------------
// Kernel 3: warp-per-node segment softmax + attention-weighted sum.
// Edge ranges are contiguous (seg_ids sorted), so no atomics.
// ---------------------------------------------------------------------------
__global__ void agg_kernel(const int* __restrict__ neigh,
                           const float* __restrict__ u2e,
                           float* __restrict__ out, int N)
{
    int gw   = (blockIdx.x * blockDim.x + threadIdx.x) >> 5;
    int lane = threadIdx.x & 31;
    if (gw >= N) return;
    int s = g_starts[gw], epos = g_starts[gw + 1];

    // pass 1: segment max
    float m = -INFINITY;
    for (int i = s + lane; i < epos; i += 32) m = fmaxf(m, g_logits[i]);
    #pragma unroll
    for (int o = 16; o; o >>= 1) m = fmaxf(m, __shfl_xor_sync(0xffffffffu, m, o));
    if (!isfinite(m)) m = 0.0f;   // empty-segment guard, matches reference

    // pass 2: exp + segment sum
    float sum = 0.0f;
    for (int i = s + lane; i < epos; i += 32) {
        float ex = __expf(g_logits[i] - m);
        g_ex[i] = ex;
        sum += ex;
    }
    #pragma unroll
    for (int o = 16; o; o >>= 1) sum += __shfl_xor_sync(0xffffffffu, sum, o);
    float inv = 1.0f / fmaxf(sum, 1e-9f);
    __syncwarp();  // makes lane-written g_ex visible warp-wide

    // pass 3: out[n,:] = sum_i att_i * e_u_i ; each lane owns dims (2*lane, 2*lane+1)
    float a0 = 0.0f, a1 = 0.0f;
    for (int i = s; i < epos; i++) {
        float att = g_ex[i] * inv;
        const float2* row = (const float2*)(u2e + (size_t)neigh[i] * 64);
        float2 v = row[lane];
        a0 = fmaf(att, v.x, a0);
        a1 = fmaf(att, v.y, a1);
    }
    ((float2*)out)[(size_t)gw * 32 + lane] = make_float2(a0, a1);
}

// ---------------------------------------------------------------------------
extern "C" void kernel_launch(void* const* d_in, const int* in_sizes, int n_in,
                              void* d_out, int out_size)
{
    const int*   nodes = (const int*)d_in[0];
    const int*   neigh = (const int*)d_in[1];
    const int*   seg   = (const int*)d_in[2];
    const float* u2e   = (const float*)d_in[3];
    const float* w1    = (const float*)d_in[4];
    const float* b1    = (const float*)d_in[5];
    const float* w2    = (const float*)d_in[6];
    const float* b2    = (const float*)d_in[7];
    const float* w3    = (const float*)d_in[8];
    const float* b3    = (const float*)d_in[9];

    int N = in_sizes[0];
    int E = in_sizes[1];
    if (E > CAP_E) E = CAP_E;
    if (N > CAP_N - 2) N = CAP_N - 2;

    starts_kernel<<<(N + 256) / 256, 256>>>(seg, E, N);

    const int smem_bytes = 49664;
    cudaFuncSetAttribute(mlp_kernel, cudaFuncAttributeMaxDynamicSharedMemorySize, smem_bytes);
    mlp_kernel<<<(E + 127) / 128, 128, smem_bytes>>>(
        nodes, neigh, seg, u2e, w1, b1, w2, b2, w3, b3, E);

    agg_kernel<<<(N * 32 + 255) / 256, 256>>>(neigh, u2e, (float*)d_out, N);
}

// round 2
// speedup vs baseline: 2.3918x; 2.3918x over previous
#include <cuda_runtime.h>
#include <math.h>

#define CAP_E 655360
#define CAP_N 20004
#define CAP_V 100352

// Scratch (allocation-free rule: __device__ globals)
__device__ float g_preA[(size_t)CAP_V * 64];   // u2e @ W1a + b1  per vocab row
__device__ float g_preB[(size_t)CAP_N * 64];   // u2e[nodes] @ W1b per center node
__device__ float g_logits[CAP_E];
__device__ float g_ex[CAP_E];

typedef unsigned long long ull;

__device__ __forceinline__ ull fma2(ull a, ull b, ull c) {
    ull d;
    asm("fma.rn.f32x2 %0, %1, %2, %3;" : "=l"(d) : "l"(a), "l"(b), "l"(c));
    return d;
}
__device__ __forceinline__ ull pack2(float lo, float hi) {
    ull r;
    asm("mov.b64 %0, {%1, %2};" : "=l"(r) : "f"(lo), "f"(hi));
    return r;
}
__device__ __forceinline__ float2 unpack2(ull v) {
    float2 r;
    asm("mov.b64 {%0, %1}, %2;" : "=f"(r.x), "=f"(r.y) : "l"(v));
    return r;
}

// ---------------------------------------------------------------------------
// Kernel 1: preA[v] = u2e[v] @ W1[0:64] + b1       (one thread per vocab row)
// W1 rows 0..63 pair-packed in smem; all weight reads warp-uniform broadcasts.
// ---------------------------------------------------------------------------
__global__ __launch_bounds__(128, 4) void preA_kernel(
    const float* __restrict__ u2e, const float* __restrict__ w1,
    const float* __restrict__ b1, int V)
{
    __shared__ ull s_w[2048];               // W1 rows 0..63, contiguous pairs
    const int tid = threadIdx.x;
    const ull* w1p = (const ull*)w1;
    for (int i = tid; i < 2048; i += 128) s_w[i] = w1p[i];
    __syncthreads();

    int v = blockIdx.x * 128 + tid;
    if (v >= V) return;

    ull acc[32];
    const ull* b1p = (const ull*)b1;
    #pragma unroll
    for (int jp = 0; jp < 32; jp++) acc[jp] = b1p[jp];

    const float4* x4 = (const float4*)(u2e + (size_t)v * 64);
    #pragma unroll 1
    for (int c = 0; c < 16; c++) {
        float4 xv = x4[c];
        float xs[4] = {xv.x, xv.y, xv.z, xv.w};
        #pragma unroll
        for (int kk = 0; kk < 4; kk++) {
            ull xx = pack2(xs[kk], xs[kk]);
            const ull* wr = &s_w[(c * 4 + kk) * 32];
            #pragma unroll
            for (int jp = 0; jp < 32; jp += 2) {
                ulonglong2 w = *(const ulonglong2*)&wr[jp];
                acc[jp]     = fma2(xx, w.x, acc[jp]);
                acc[jp + 1] = fma2(xx, w.y, acc[jp + 1]);
            }
        }
    }
    ull* outp = (ull*)(g_preA + (size_t)v * 64);
    #pragma unroll
    for (int jp = 0; jp < 32; jp++) outp[jp] = acc[jp];
}

// ---------------------------------------------------------------------------
// Kernel 2: preB[n] = u2e[nodes[n]] @ W1[64:128]   (one thread per node)
// ---------------------------------------------------------------------------
__global__ __launch_bounds__(128, 4) void preB_kernel(
    const int* __restrict__ nodes, const float* __restrict__ u2e,
    const float* __restrict__ w1, int N)
{
    __shared__ ull s_w[2048];               // W1 rows 64..127
    const int tid = threadIdx.x;
    const ull* w1p = (const ull*)w1 + 2048;
    for (int i = tid; i < 2048; i += 128) s_w[i] = w1p[i];
    __syncthreads();

    int n = blockIdx.x * 128 + tid;
    if (n >= N) return;

    ull acc[32];
    #pragma unroll
    for (int jp = 0; jp < 32; jp++) acc[jp] = 0ull;

    const float4* x4 = (const float4*)(u2e + (size_t)nodes[n] * 64);
    #pragma unroll 1
    for (int c = 0; c < 16; c++) {
        float4 xv = x4[c];
        float xs[4] = {xv.x, xv.y, xv.z, xv.w};
        #pragma unroll
        for (int kk = 0; kk < 4; kk++) {
            ull xx = pack2(xs[kk], xs[kk]);
            const ull* wr = &s_w[(c * 4 + kk) * 32];
            #pragma unroll
            for (int jp = 0; jp < 32; jp += 2) {
                ulonglong2 w = *(const ulonglong2*)&wr[jp];
                acc[jp]     = fma2(xx, w.x, acc[jp]);
                acc[jp + 1] = fma2(xx, w.y, acc[jp + 1]);
            }
        }
    }
    ull* outp = (ull*)(g_preB + (size_t)n * 64);
    #pragma unroll
    for (int jp = 0; jp < 32; jp++) outp[jp] = acc[jp];
}

// ---------------------------------------------------------------------------
// Kernel 3: per-edge: h1 = relu(preA[neigh] + preB[seg]);
//           layer2 (64x64) + layer3 fused -> logit.  One thread per edge.
// W2 pair-packed k-major in smem (raw copy: W2 is [64][64] row-major).
// ---------------------------------------------------------------------------
__global__ __launch_bounds__(128, 4) void edge_kernel(
    const int* __restrict__ neigh, const int* __restrict__ seg,
    const float* __restrict__ w2, const float* __restrict__ b2,
    const float* __restrict__ w3, const float* __restrict__ b3,
    int E)
{
    __shared__ ull s_w2[2048];              // W2[k][jpair], contiguous pairs
    __shared__ ull s_w3[32];                // w3 pairs
    const int tid = threadIdx.x;
    const ull* w2p = (const ull*)w2;
    for (int i = tid; i < 2048; i += 128) s_w2[i] = w2p[i];
    if (tid < 32) s_w3[tid] = ((const ull*)w3)[tid];
    __syncthreads();

    int e = blockIdx.x * 128 + tid;
    if (e >= E) return;

    const int nb = neigh[e];
    const int sg = seg[e];

    ull acc[32];
    const ull* b2p = (const ull*)b2;
    #pragma unroll
    for (int jp = 0; jp < 32; jp++) acc[jp] = b2p[jp];

    const float4* a4 = (const float4*)(g_preA + (size_t)nb * 64);
    const float4* bb4 = (const float4*)(g_preB + (size_t)sg * 64);

    #pragma unroll 1
    for (int c = 0; c < 16; c++) {
        float4 av = a4[c];
        float4 bv = bb4[c];
        float hs[4] = {fmaxf(av.x + bv.x, 0.0f), fmaxf(av.y + bv.y, 0.0f),
                       fmaxf(av.z + bv.z, 0.0f), fmaxf(av.w + bv.w, 0.0f)};
        #pragma unroll
        for (int kk = 0; kk < 4; kk++) {
            ull xx = pack2(hs[kk], hs[kk]);
            const ull* wr = &s_w2[(c * 4 + kk) * 32];
            #pragma unroll
            for (int jp = 0; jp < 32; jp += 2) {
                ulonglong2 w = *(const ulonglong2*)&wr[jp];
                acc[jp]     = fma2(xx, w.x, acc[jp]);
                acc[jp + 1] = fma2(xx, w.y, acc[jp + 1]);
            }
        }
    }

    // layer 3: logit = b3 + sum_j relu(h2_j) * w3_j   (packed accumulate)
    ull tacc = 0ull;
    #pragma unroll
    for (int jp = 0; jp < 32; jp++) {
        float2 v = unpack2(acc[jp]);
        ull rel = pack2(fmaxf(v.x, 0.0f), fmaxf(v.y, 0.0f));
        tacc = fma2(rel, s_w3[jp], tacc);
    }
    float2 t = unpack2(tacc);
    g_logits[e] = t.x + t.y + b3[0];
}

// ---------------------------------------------------------------------------
// Kernel 4: warp-per-node segment softmax + attention-weighted sum.
// Edge ranges found by in-warp binary search on the sorted seg_ids.
// ---------------------------------------------------------------------------
__global__ void agg_kernel(const int* __restrict__ neigh,
                           const int* __restrict__ seg,
                           const float* __restrict__ u2e,
                           float* __restrict__ out, int N, int E)
{
    int gw   = (blockIdx.x * blockDim.x + threadIdx.x) >> 5;
    int lane = threadIdx.x & 31;
    if (gw >= N) return;

    // lanes 0,1 find lower_bound(seg, gw) and lower_bound(seg, gw+1)
    int bound = E;
    if (lane < 2) {
        int target = gw + lane;
        int lo = 0, hi = E;
        while (lo < hi) {
            int mid = (lo + hi) >> 1;
            if (seg[mid] < target) lo = mid + 1; else hi = mid;
        }
        bound = lo;
    }
    int s    = __shfl_sync(0xffffffffu, bound, 0);
    int epos = __shfl_sync(0xffffffffu, bound, 1);

    // pass 1: segment max
    float m = -INFINITY;
    for (int i = s + lane; i < epos; i += 32) m = fmaxf(m, g_logits[i]);
    #pragma unroll
    for (int o = 16; o; o >>= 1) m = fmaxf(m, __shfl_xor_sync(0xffffffffu, m, o));
    if (!isfinite(m)) m = 0.0f;   // empty-segment guard, matches reference

    // pass 2: exp + segment sum
    float sum = 0.0f;
    for (int i = s + lane; i < epos; i += 32) {
        float ex = __expf(g_logits[i] - m);
        g_ex[i] = ex;
        sum += ex;
    }
    #pragma unroll
    for (int o = 16; o; o >>= 1) sum += __shfl_xor_sync(0xffffffffu, sum, o);
    float inv = 1.0f / fmaxf(sum, 1e-9f);
    __syncwarp();  // lane-written g_ex visible warp-wide

    // pass 3: out[n,:] = sum_i att_i * e_u_i ; lane owns dims (2*lane, 2*lane+1)
    float a0 = 0.0f, a1 = 0.0f;
    for (int i = s; i < epos; i++) {
        float att = g_ex[i] * inv;
        const float2* row = (const float2*)(u2e + (size_t)neigh[i] * 64);
        float2 v = row[lane];
        a0 = fmaf(att, v.x, a0);
        a1 = fmaf(att, v.y, a1);
    }
    ((float2*)out)[(size_t)gw * 32 + lane] = make_float2(a0, a1);
}

// ---------------------------------------------------------------------------
extern "C" void kernel_launch(void* const* d_in, const int* in_sizes, int n_in,
                              void* d_out, int out_size)
{
    const int*   nodes = (const int*)d_in[0];
    const int*   neigh = (const int*)d_in[1];
    const int*   seg   = (const int*)d_in[2];
    const float* u2e   = (const float*)d_in[3];
    const float* w1    = (const float*)d_in[4];
    const float* b1    = (const float*)d_in[5];
    const float* w2    = (const float*)d_in[6];
    const float* b2    = (const float*)d_in[7];
    const float* w3    = (const float*)d_in[8];
    const float* b3    = (const float*)d_in[9];

    int N = in_sizes[0];
    int E = in_sizes[1];
    int V = in_sizes[3] / 64;
    if (E > CAP_E) E = CAP_E;
    if (N > CAP_N - 2) N = CAP_N - 2;
    if (V > CAP_V) V = CAP_V;

    preA_kernel<<<(V + 127) / 128, 128>>>(u2e, w1, b1, V);
    preB_kernel<<<(N + 127) / 128, 128>>>(nodes, u2e, w1, N);
    edge_kernel<<<(E + 127) / 128, 128>>>(neigh, seg, w2, b2, w3, b3, E);
    agg_kernel<<<(N * 32 + 255) / 256, 256>>>(neigh, seg, u2e, (float*)d_out, N, E);
}

// round 4
// speedup vs baseline: 4.4906x; 1.8775x over previous
#include <cuda_runtime.h>
#include <cuda_bf16.h>
#include <cstdint>
#include <math.h>

#define CAP_E 655360
#define CAP_N 20004
#define CAP_V 100352

// Scratch (allocation-free rule: __device__ globals)
__device__ float g_preA[(size_t)CAP_V * 64];   // u2e @ W1a + b1  per vocab row
__device__ float g_preB[(size_t)CAP_N * 64];   // u2e[nodes] @ W1b per center node
__device__ float g_logits[CAP_E];
__device__ float g_ex[CAP_E];

typedef unsigned long long ull;

__device__ __forceinline__ ull fma2(ull a, ull b, ull c) {
    ull d;
    asm("fma.rn.f32x2 %0, %1, %2, %3;" : "=l"(d) : "l"(a), "l"(b), "l"(c));
    return d;
}
__device__ __forceinline__ ull pack2(float lo, float hi) {
    ull r;
    asm("mov.b64 %0, {%1, %2};" : "=l"(r) : "f"(lo), "f"(hi));
    return r;
}
__device__ __forceinline__ uint32_t pack_bf2(float lo, float hi) {
    uint32_t r;
    asm("cvt.rn.bf16x2.f32 %0, %1, %2;" : "=r"(r) : "f"(hi), "f"(lo));
    return r;
}
// Split (x,y) into bf16x2 hi + bf16x2 residual
__device__ __forceinline__ void split_bf(float x, float y, uint32_t& hi, uint32_t& lo) {
    __nv_bfloat16 bx = __float2bfloat16(x);
    __nv_bfloat16 by = __float2bfloat16(y);
    __nv_bfloat162 h(bx, by);
    hi = *reinterpret_cast<uint32_t*>(&h);
    lo = pack_bf2(x - __bfloat162float(bx), y - __bfloat162float(by));
}
__device__ __forceinline__ void mma_16816(float* c, uint32_t a0, uint32_t a1,
                                          uint32_t a2, uint32_t a3,
                                          uint32_t b0, uint32_t b1) {
    asm volatile(
        "mma.sync.aligned.m16n8k16.row.col.f32.bf16.bf16.f32 "
        "{%0,%1,%2,%3}, {%4,%5,%6,%7}, {%8,%9}, {%0,%1,%2,%3};"
        : "+f"(c[0]), "+f"(c[1]), "+f"(c[2]), "+f"(c[3])
        : "r"(a0), "r"(a1), "r"(a2), "r"(a3), "r"(b0), "r"(b1));
}

// ---------------------------------------------------------------------------
// Kernel 1: preA[v] = u2e[v] @ W1[0:64] + b1       (one thread per vocab row)
// ---------------------------------------------------------------------------
__global__ __launch_bounds__(128, 4) void preA_kernel(
    const float* __restrict__ u2e, const float* __restrict__ w1,
    const float* __restrict__ b1, int V)
{
    __shared__ ull s_w[2048];
    const int tid = threadIdx.x;
    const ull* w1p = (const ull*)w1;
    for (int i = tid; i < 2048; i += 128) s_w[i] = w1p[i];
    __syncthreads();

    int v = blockIdx.x * 128 + tid;
    if (v >= V) return;

    ull acc[32];
    const ull* b1p = (const ull*)b1;
    #pragma unroll
    for (int jp = 0; jp < 32; jp++) acc[jp] = b1p[jp];

    const float4* x4 = (const float4*)(u2e + (size_t)v * 64);
    #pragma unroll 1
    for (int c = 0; c < 16; c++) {
        float4 xv = x4[c];
        float xs[4] = {xv.x, xv.y, xv.z, xv.w};
        #pragma unroll
        for (int kk = 0; kk < 4; kk++) {
            ull xx = pack2(xs[kk], xs[kk]);
            const ull* wr = &s_w[(c * 4 + kk) * 32];
            #pragma unroll
            for (int jp = 0; jp < 32; jp += 2) {
                ulonglong2 w = *(const ulonglong2*)&wr[jp];
                acc[jp]     = fma2(xx, w.x, acc[jp]);
                acc[jp + 1] = fma2(xx, w.y, acc[jp + 1]);
            }
        }
    }
    ull* outp = (ull*)(g_preA + (size_t)v * 64);
    #pragma unroll
    for (int jp = 0; jp < 32; jp++) outp[jp] = acc[jp];
}

// ---------------------------------------------------------------------------
// Kernel 2: preB[n] = u2e[nodes[n]] @ W1[64:128]   (one thread per node)
// ---------------------------------------------------------------------------
__global__ __launch_bounds__(128, 4) void preB_kernel(
    const int* __restrict__ nodes, const float* __restrict__ u2e,
    const float* __restrict__ w1, int N)
{
    __shared__ ull s_w[2048];
    const int tid = threadIdx.x;
    const ull* w1p = (const ull*)w1 + 2048;
    for (int i = tid; i < 2048; i += 128) s_w[i] = w1p[i];
    __syncthreads();

    int n = blockIdx.x * 128 + tid;
    if (n >= N) return;

    ull acc[32];
    #pragma unroll
    for (int jp = 0; jp < 32; jp++) acc[jp] = 0ull;

    const float4* x4 = (const float4*)(u2e + (size_t)nodes[n] * 64);
    #pragma unroll 1
    for (int c = 0; c < 16; c++) {
        float4 xv = x4[c];
        float xs[4] = {xv.x, xv.y, xv.z, xv.w};
        #pragma unroll
        for (int kk = 0; kk < 4; kk++) {
            ull xx = pack2(xs[kk], xs[kk]);
            const ull* wr = &s_w[(c * 4 + kk) * 32];
            #pragma unroll
            for (int jp = 0; jp < 32; jp += 2) {
                ulonglong2 w = *(const ulonglong2*)&wr[jp];
                acc[jp]     = fma2(xx, w.x, acc[jp]);
                acc[jp + 1] = fma2(xx, w.y, acc[jp + 1]);
            }
        }
    }
    ull* outp = (ull*)(g_preB + (size_t)n * 64);
    #pragma unroll
    for (int jp = 0; jp < 32; jp++) outp[jp] = acc[jp];
}

// ---------------------------------------------------------------------------
// Kernel 3 (mma.sync): per warp-tile of 16 edges:
//   A[16,64] = relu(preA[neigh]+preB[seg])  (bf16 hi + residual lo, registers)
//   H2 = Ah@W2h + Al@W2h   via m16n8k16 HMMA, fp32 accum in registers
//   logit[e] = b3 + sum_j relu(H2[e][j] + b2[j]) * w3[j]
// No smem staging for A/C, no barriers in the main loop.
// ---------------------------------------------------------------------------
__global__ __launch_bounds__(256) void edge_mma_kernel(
    const int* __restrict__ neigh, const int* __restrict__ seg,
    const float* __restrict__ w2, const float* __restrict__ b2,
    const float* __restrict__ w3, const float* __restrict__ b3,
    int E, int ntiles)
{
    __shared__ float s_w2[4096];
    __shared__ float s_b2[64];
    __shared__ float s_w3[64];
    __shared__ float s_b3;

    const int tid  = threadIdx.x;
    const int lane = tid & 31;
    const int wid  = tid >> 5;
    const int g    = lane >> 2;        // groupID: row within tile
    const int tig  = lane & 3;         // thread-in-group

    // Stage W2 (16KB) + b2/w3/b3 into smem (coalesced)
    const float4* w2v = (const float4*)w2;
    for (int i = tid; i < 1024; i += 256) ((float4*)s_w2)[i] = w2v[i];
    if (tid < 64) { s_b2[tid] = b2[tid]; s_w3[tid] = w3[tid]; }
    if (tid == 255) s_b3 = b3[0];
    __syncthreads();

    // Build bf16 B fragments for all (kc, nc): b0 = {W2[k0][n], W2[k0+1][n]},
    // b1 = {W2[k0+8][n], W2[k0+9][n]}  with n = nc*8 + g, k0 = kc*16 + 2*tig.
    uint32_t Bf[4][8][2];
    #pragma unroll
    for (int kc = 0; kc < 4; kc++) {
        int k0 = kc * 16 + 2 * tig;
        #pragma unroll
        for (int nc = 0; nc < 8; nc++) {
            int n = nc * 8 + g;
            Bf[kc][nc][0] = pack_bf2(s_w2[k0 * 64 + n],       s_w2[(k0 + 1) * 64 + n]);
            Bf[kc][nc][1] = pack_bf2(s_w2[(k0 + 8) * 64 + n], s_w2[(k0 + 9) * 64 + n]);
        }
    }
    const float vb3 = s_b3;

    const int warp_gid = blockIdx.x * 8 + wid;
    const int nwarps   = gridDim.x * 8;

    for (int tile = warp_gid; tile < ntiles; tile += nwarps) {
        const int base = tile * 16;
        const int e0 = base + g;       // this thread's row 0 edge
        const int e1 = e0 + 8;         // row 1 edge
        const int ee0 = e0 < E ? e0 : E - 1;
        const int ee1 = e1 < E ? e1 : E - 1;

        const float2* pa0 = (const float2*)(g_preA + (size_t)neigh[ee0] * 64);
        const float2* pb0 = (const float2*)(g_preB + (size_t)seg[ee0] * 64);
        const float2* pa1 = (const float2*)(g_preA + (size_t)neigh[ee1] * 64);
        const float2* pb1 = (const float2*)(g_preB + (size_t)seg[ee1] * 64);

        float c[8][4];
        #pragma unroll
        for (int nc = 0; nc < 8; nc++) {
            c[nc][0] = 0.f; c[nc][1] = 0.f; c[nc][2] = 0.f; c[nc][3] = 0.f;
        }

        #pragma unroll
        for (int kc = 0; kc < 4; kc++) {
            const int i0 = kc * 8 + tig;     // float2 index: cols 2*tig, 2*tig+1
            const int i1 = i0 + 4;           // cols +8
            float2 xa0 = pa0[i0], xb0 = pb0[i0];
            float2 xa1 = pa0[i1], xb1 = pb0[i1];
            float2 ya0 = pa1[i0], yb0 = pb1[i0];
            float2 ya1 = pa1[i1], yb1 = pb1[i1];

            uint32_t a0, a1, a2, a3, l0, l1, l2, l3;
            split_bf(fmaxf(xa0.x + xb0.x, 0.f), fmaxf(xa0.y + xb0.y, 0.f), a0, l0);
            split_bf(fmaxf(ya0.x + yb0.x, 0.f), fmaxf(ya0.y + yb0.y, 0.f), a1, l1);
            split_bf(fmaxf(xa1.x + xb1.x, 0.f), fmaxf(xa1.y + xb1.y, 0.f), a2, l2);
            split_bf(fmaxf(ya1.x + yb1.x, 0.f), fmaxf(ya1.y + yb1.y, 0.f), a3, l3);

            #pragma unroll
            for (int nc = 0; nc < 8; nc++) {
                mma_16816(c[nc], a0, a1, a2, a3, Bf[kc][nc][0], Bf[kc][nc][1]);
                mma_16816(c[nc], l0, l1, l2, l3, Bf[kc][nc][0], Bf[kc][nc][1]);
            }
        }

        // Epilogue: logit = b3 + sum_j relu(h2_j + b2_j) * w3_j
        float p0 = 0.f, p1 = 0.f;
        #pragma unroll
        for (int nc = 0; nc < 8; nc++) {
            const int col0 = nc * 8 + 2 * tig;
            const int col1 = col0 + 1;
            const float bb0 = s_b2[col0], bb1 = s_b2[col1];
            const float ww0 = s_w3[col0], ww1 = s_w3[col1];
            p0 = fmaf(fmaxf(c[nc][0] + bb0, 0.f), ww0, p0);
            p0 = fmaf(fmaxf(c[nc][1] + bb1, 0.f), ww1, p0);
            p1 = fmaf(fmaxf(c[nc][2] + bb0, 0.f), ww0, p1);
            p1 = fmaf(fmaxf(c[nc][3] + bb1, 0.f), ww1, p1);
        }
        p0 += __shfl_xor_sync(0xffffffffu, p0, 1);
        p0 += __shfl_xor_sync(0xffffffffu, p0, 2);
        p1 += __shfl_xor_sync(0xffffffffu, p1, 1);
        p1 += __shfl_xor_sync(0xffffffffu, p1, 2);

        if (tig == 0) {
            if (e0 < E) g_logits[e0] = p0 + vb3;
            if (e1 < E) g_logits[e1] = p1 + vb3;
        }
    }
}

// ---------------------------------------------------------------------------
// Kernel 4: warp-per-node segment softmax + attention-weighted sum.
// ---------------------------------------------------------------------------
__global__ void agg_kernel(const int* __restrict__ neigh,
                           const int* __restrict__ seg,
                           const float* __restrict__ u2e,
                           float* __restrict__ out, int N, int E)
{
    int gw   = (blockIdx.x * blockDim.x + threadIdx.x) >> 5;
    int lane = threadIdx.x & 31;
    if (gw >= N) return;

    int bound = E;
    if (lane < 2) {
        int target = gw + lane;
        int lo = 0, hi = E;
        while (lo < hi) {
            int mid = (lo + hi) >> 1;
            if (seg[mid] < target) lo = mid + 1; else hi = mid;
        }
        bound = lo;
    }
    int s    = __shfl_sync(0xffffffffu, bound, 0);
    int epos = __shfl_sync(0xffffffffu, bound, 1);

    float m = -INFINITY;
    for (int i = s + lane; i < epos; i += 32) m = fmaxf(m, g_logits[i]);
    #pragma unroll
    for (int o = 16; o; o >>= 1) m = fmaxf(m, __shfl_xor_sync(0xffffffffu, m, o));
    if (!isfinite(m)) m = 0.0f;

    float sum = 0.0f;
    for (int i = s + lane; i < epos; i += 32) {
        float ex = __expf(g_logits[i] - m);
        g_ex[i] = ex;
        sum += ex;
    }
    #pragma unroll
    for (int o = 16; o; o >>= 1) sum += __shfl_xor_sync(0xffffffffu, sum, o);
    float inv = 1.0f / fmaxf(sum, 1e-9f);
    __syncwarp();

    float a0 = 0.0f, a1 = 0.0f;
    for (int i = s; i < epos; i++) {
        float att = g_ex[i] * inv;
        const float2* row = (const float2*)(u2e + (size_t)neigh[i] * 64);
        float2 v = row[lane];
        a0 = fmaf(att, v.x, a0);
        a1 = fmaf(att, v.y, a1);
    }
    ((float2*)out)[(size_t)gw * 32 + lane] = make_float2(a0, a1);
}

// ---------------------------------------------------------------------------
extern "C" void kernel_launch(void* const* d_in, const int* in_sizes, int n_in,
                              void* d_out, int out_size)
{
    const int*   nodes = (const int*)d_in[0];
    const int*   neigh = (const int*)d_in[1];
    const int*   seg   = (const int*)d_in[2];
    const float* u2e   = (const float*)d_in[3];
    const float* w1    = (const float*)d_in[4];
    const float* b1    = (const float*)d_in[5];
    const float* w2    = (const float*)d_in[6];
    const float* b2    = (const float*)d_in[7];
    const float* w3    = (const float*)d_in[8];
    const float* b3    = (const float*)d_in[9];

    int N = in_sizes[0];
    int E = in_sizes[1];
    int V = in_sizes[3] / 64;
    if (E > CAP_E) E = CAP_E;
    if (N > CAP_N - 2) N = CAP_N - 2;
    if (V > CAP_V) V = CAP_V;

    preA_kernel<<<(V + 127) / 128, 128>>>(u2e, w1, b1, V);
    preB_kernel<<<(N + 127) / 128, 128>>>(nodes, u2e, w1, N);

    int ntiles = (E + 15) / 16;
    int grid = 296;
    int maxgrid = (ntiles + 7) / 8;
    if (grid > maxgrid) grid = maxgrid;
    edge_mma_kernel<<<grid, 256>>>(neigh, seg, w2, b2, w3, b3, E, ntiles);

    agg_kernel<<<(N * 32 + 255) / 256, 256>>>(neigh, seg, u2e, (float*)d_out, N, E);
}

// round 5
// speedup vs baseline: 6.3139x; 1.4060x over previous
#include <cuda_runtime.h>
#include <cuda_bf16.h>
#include <cstdint>
#include <math.h>

#define CAP_E 655360
#define CAP_N 20004
#define CAP_V 100352

// Scratch (allocation-free rule: __device__ globals)
// preA/preB stored as packed bf16x2: 32 uint32 per row (64 cols)
__device__ uint32_t g_preA[(size_t)CAP_V * 32];
__device__ uint32_t g_preB[(size_t)CAP_N * 32];
__device__ float g_logits[CAP_E];
__device__ float g_ex[CAP_E];

typedef unsigned long long ull;

__device__ __forceinline__ ull fma2(ull a, ull b, ull c) {
    ull d;
    asm("fma.rn.f32x2 %0, %1, %2, %3;" : "=l"(d) : "l"(a), "l"(b), "l"(c));
    return d;
}
__device__ __forceinline__ ull pack2(float lo, float hi) {
    ull r;
    asm("mov.b64 %0, {%1, %2};" : "=l"(r) : "f"(lo), "f"(hi));
    return r;
}
__device__ __forceinline__ float2 unpack2(ull v) {
    float2 r;
    asm("mov.b64 {%0, %1}, %2;" : "=f"(r.x), "=f"(r.y) : "l"(v));
    return r;
}
// lower half <- lo, upper half <- hi
__device__ __forceinline__ uint32_t pack_bf2(float lo, float hi) {
    uint32_t r;
    asm("cvt.rn.bf16x2.f32 %0, %1, %2;" : "=r"(r) : "f"(hi), "f"(lo));
    return r;
}
// bf16x2: relu(a + b)
__device__ __forceinline__ uint32_t hadd_relu2(uint32_t a, uint32_t b) {
    __nv_bfloat162 av = *reinterpret_cast<__nv_bfloat162*>(&a);
    __nv_bfloat162 bv = *reinterpret_cast<__nv_bfloat162*>(&b);
    __nv_bfloat162 z = __float2bfloat162_rn(0.0f);
    __nv_bfloat162 r = __hmax2(__hadd2(av, bv), z);
    return *reinterpret_cast<uint32_t*>(&r);
}
__device__ __forceinline__ void mma_16816(float* c, uint32_t a0, uint32_t a1,
                                          uint32_t a2, uint32_t a3,
                                          uint32_t b0, uint32_t b1) {
    asm volatile(
        "mma.sync.aligned.m16n8k16.row.col.f32.bf16.bf16.f32 "
        "{%0,%1,%2,%3}, {%4,%5,%6,%7}, {%8,%9}, {%0,%1,%2,%3};"
        : "+f"(c[0]), "+f"(c[1]), "+f"(c[2]), "+f"(c[3])
        : "r"(a0), "r"(a1), "r"(a2), "r"(a3), "r"(b0), "r"(b1));
}

// ---------------------------------------------------------------------------
// Kernel 1 (merged): blocks [0, nbA) compute preA rows; blocks [nbA, ...)
// compute preB rows. Output packed bf16x2.
// ---------------------------------------------------------------------------
__global__ __launch_bounds__(128, 4) void pre_kernel(
    const int* __restrict__ nodes, const float* __restrict__ u2e,
    const float* __restrict__ w1, const float* __restrict__ b1,
    int V, int N, int nbA)
{
    __shared__ ull s_w[2048];
    const int tid = threadIdx.x;
    const bool isA = blockIdx.x < nbA;

    const ull* w1p = (const ull*)w1 + (isA ? 0 : 2048);
    for (int i = tid; i < 2048; i += 128) s_w[i] = w1p[i];
    __syncthreads();

    int row, src;
    if (isA) {
        row = blockIdx.x * 128 + tid;
        if (row >= V) return;
        src = row;
    } else {
        row = (blockIdx.x - nbA) * 128 + tid;
        if (row >= N) return;
        src = nodes[row];
    }

    ull acc[32];
    if (isA) {
        const ull* b1p = (const ull*)b1;
        #pragma unroll
        for (int jp = 0; jp < 32; jp++) acc[jp] = b1p[jp];
    } else {
        #pragma unroll
        for (int jp = 0; jp < 32; jp++) acc[jp] = 0ull;
    }

    const float4* x4 = (const float4*)(u2e + (size_t)src * 64);
    #pragma unroll 1
    for (int c = 0; c < 16; c++) {
        float4 xv = x4[c];
        float xs[4] = {xv.x, xv.y, xv.z, xv.w};
        #pragma unroll
        for (int kk = 0; kk < 4; kk++) {
            ull xx = pack2(xs[kk], xs[kk]);
            const ull* wr = &s_w[(c * 4 + kk) * 32];
            #pragma unroll
            for (int jp = 0; jp < 32; jp += 2) {
                ulonglong2 w = *(const ulonglong2*)&wr[jp];
                acc[jp]     = fma2(xx, w.x, acc[jp]);
                acc[jp + 1] = fma2(xx, w.y, acc[jp + 1]);
            }
        }
    }

    uint32_t packed[32];
    #pragma unroll
    for (int jp = 0; jp < 32; jp++) {
        float2 v = unpack2(acc[jp]);
        packed[jp] = pack_bf2(v.x, v.y);
    }
    uint4* outp = (uint4*)((isA ? g_preA : g_preB) + (size_t)row * 32);
    #pragma unroll
    for (int q = 0; q < 8; q++) outp[q] = ((uint4*)packed)[q];
}

// ---------------------------------------------------------------------------
// Kernel 2 (mma.sync): per warp-tile of 16 edges:
//   A[16,64] = relu(preA_bf[neigh] + preB_bf[seg])   (bf16x2 loads, 2 HALU ops)
//   H2 = A @ W2_bf16  via m16n8k16 HMMA, fp32 accum
//   logit[e] = b3 + sum_j relu(H2[e][j] + b2[j]) * w3[j]
// ---------------------------------------------------------------------------
__global__ __launch_bounds__(256) void edge_mma_kernel(
    const int* __restrict__ neigh, const int* __restrict__ seg,
    const float* __restrict__ w2, const float* __restrict__ b2,
    const float* __restrict__ w3, const float* __restrict__ b3,
    int E, int ntiles)
{
    __shared__ float s_w2[4096];
    __shared__ float s_b2[64];
    __shared__ float s_w3[64];
    __shared__ float s_b3;

    const int tid  = threadIdx.x;
    const int lane = tid & 31;
    const int wid  = tid >> 5;
    const int g    = lane >> 2;        // row within 8-row group
    const int tig  = lane & 3;         // thread-in-group

    const float4* w2v = (const float4*)w2;
    for (int i = tid; i < 1024; i += 256) ((float4*)s_w2)[i] = w2v[i];
    if (tid < 64) { s_b2[tid] = b2[tid]; s_w3[tid] = w3[tid]; }
    if (tid == 255) s_b3 = b3[0];
    __syncthreads();

    // B fragments: b0 = {W2[k0][n], W2[k0+1][n]}, b1 = {W2[k0+8][n], W2[k0+9][n]}
    uint32_t Bf[4][8][2];
    #pragma unroll
    for (int kc = 0; kc < 4; kc++) {
        int k0 = kc * 16 + 2 * tig;
        #pragma unroll
        for (int nc = 0; nc < 8; nc++) {
            int n = nc * 8 + g;
            Bf[kc][nc][0] = pack_bf2(s_w2[k0 * 64 + n],       s_w2[(k0 + 1) * 64 + n]);
            Bf[kc][nc][1] = pack_bf2(s_w2[(k0 + 8) * 64 + n], s_w2[(k0 + 9) * 64 + n]);
        }
    }
    const float vb3 = s_b3;

    const int warp_gid = blockIdx.x * 8 + wid;
    const int nwarps   = gridDim.x * 8;

    for (int tile = warp_gid; tile < ntiles; tile += nwarps) {
        const int base = tile * 16;
        const int e0 = base + g;
        const int e1 = e0 + 8;
        const int ee0 = e0 < E ? e0 : E - 1;
        const int ee1 = e1 < E ? e1 : E - 1;

        const uint32_t* pa0 = g_preA + (size_t)neigh[ee0] * 32;
        const uint32_t* pb0 = g_preB + (size_t)seg[ee0] * 32;
        const uint32_t* pa1 = g_preA + (size_t)neigh[ee1] * 32;
        const uint32_t* pb1 = g_preB + (size_t)seg[ee1] * 32;

        float c[8][4];
        #pragma unroll
        for (int nc = 0; nc < 8; nc++) {
            c[nc][0] = 0.f; c[nc][1] = 0.f; c[nc][2] = 0.f; c[nc][3] = 0.f;
        }

        #pragma unroll
        for (int kc = 0; kc < 4; kc++) {
            const int i0 = kc * 8 + tig;    // u32 index: cols 2tig..2tig+1
            const int i1 = i0 + 4;          // cols +8
            uint32_t a0 = hadd_relu2(pa0[i0], pb0[i0]);
            uint32_t a1 = hadd_relu2(pa1[i0], pb1[i0]);
            uint32_t a2 = hadd_relu2(pa0[i1], pb0[i1]);
            uint32_t a3 = hadd_relu2(pa1[i1], pb1[i1]);

            #pragma unroll
            for (int nc = 0; nc < 8; nc++)
                mma_16816(c[nc], a0, a1, a2, a3, Bf[kc][nc][0], Bf[kc][nc][1]);
        }

        // Epilogue: logit = b3 + sum_j relu(h2_j + b2_j) * w3_j
        float p0 = 0.f, p1 = 0.f;
        #pragma unroll
        for (int nc = 0; nc < 8; nc++) {
            const int col0 = nc * 8 + 2 * tig;
            const int col1 = col0 + 1;
            const float bb0 = s_b2[col0], bb1 = s_b2[col1];
            const float ww0 = s_w3[col0], ww1 = s_w3[col1];
            p0 = fmaf(fmaxf(c[nc][0] + bb0, 0.f), ww0, p0);
            p0 = fmaf(fmaxf(c[nc][1] + bb1, 0.f), ww1, p0);
            p1 = fmaf(fmaxf(c[nc][2] + bb0, 0.f), ww0, p1);
            p1 = fmaf(fmaxf(c[nc][3] + bb1, 0.f), ww1, p1);
        }
        p0 += __shfl_xor_sync(0xffffffffu, p0, 1);
        p0 += __shfl_xor_sync(0xffffffffu, p0, 2);
        p1 += __shfl_xor_sync(0xffffffffu, p1, 1);
        p1 += __shfl_xor_sync(0xffffffffu, p1, 2);

        if (tig == 0) {
            if (e0 < E) g_logits[e0] = p0 + vb3;
            if (e1 < E) g_logits[e1] = p1 + vb3;
        }
    }
}

// ---------------------------------------------------------------------------
// Kernel 3: warp-per-node segment softmax + attention-weighted sum.
// ---------------------------------------------------------------------------
__global__ void agg_kernel(const int* __restrict__ neigh,
                           const int* __restrict__ seg,
                           const float* __restrict__ u2e,
                           float* __restrict__ out, int N, int E)
{
    int gw   = (blockIdx.x * blockDim.x + threadIdx.x) >> 5;
    int lane = threadIdx.x & 31;
    if (gw >= N) return;

    int bound = E;
    if (lane < 2) {
        int target = gw + lane;
        int lo = 0, hi = E;
        while (lo < hi) {
            int mid = (lo + hi) >> 1;
            if (seg[mid] < target) lo = mid + 1; else hi = mid;
        }
        bound = lo;
    }
    int s    = __shfl_sync(0xffffffffu, bound, 0);
    int epos = __shfl_sync(0xffffffffu, bound, 1);

    float m = -INFINITY;
    for (int i = s + lane; i < epos; i += 32) m = fmaxf(m, g_logits[i]);
    #pragma unroll
    for (int o = 16; o; o >>= 1) m = fmaxf(m, __shfl_xor_sync(0xffffffffu, m, o));
    if (!isfinite(m)) m = 0.0f;

    float sum = 0.0f;
    for (int i = s + lane; i < epos; i += 32) {
        float ex = __expf(g_logits[i] - m);
        g_ex[i] = ex;
        sum += ex;
    }
    #pragma unroll
    for (int o = 16; o; o >>= 1) sum += __shfl_xor_sync(0xffffffffu, sum, o);
    float inv = 1.0f / fmaxf(sum, 1e-9f);
    __syncwarp();

    // pass 3, unrolled x2 with independent accumulators for load MLP
    float a0 = 0.0f, a1 = 0.0f, b0 = 0.0f, b1 = 0.0f;
    int i = s;
    for (; i + 1 < epos; i += 2) {
        float att0 = g_ex[i] * inv;
        float att1 = g_ex[i + 1] * inv;
        const float2* r0 = (const float2*)(u2e + (size_t)neigh[i] * 64);
        const float2* r1 = (const float2*)(u2e + (size_t)neigh[i + 1] * 64);
        float2 v0 = r0[lane];
        float2 v1 = r1[lane];
        a0 = fmaf(att0, v0.x, a0);
        a1 = fmaf(att0, v0.y, a1);
        b0 = fmaf(att1, v1.x, b0);
        b1 = fmaf(att1, v1.y, b1);
    }
    if (i < epos) {
        float att = g_ex[i] * inv;
        const float2* r = (const float2*)(u2e + (size_t)neigh[i] * 64);
        float2 v = r[lane];
        a0 = fmaf(att, v.x, a0);
        a1 = fmaf(att, v.y, a1);
    }
    ((float2*)out)[(size_t)gw * 32 + lane] = make_float2(a0 + b0, a1 + b1);
}

// ---------------------------------------------------------------------------
extern "C" void kernel_launch(void* const* d_in, const int* in_sizes, int n_in,
                              void* d_out, int out_size)
{
    const int*   nodes = (const int*)d_in[0];
    const int*   neigh = (const int*)d_in[1];
    const int*   seg   = (const int*)d_in[2];
    const float* u2e   = (const float*)d_in[3];
    const float* w1    = (const float*)d_in[4];
    const float* b1    = (const float*)d_in[5];
    const float* w2    = (const float*)d_in[6];
    const float* b2    = (const float*)d_in[7];
    const float* w3    = (const float*)d_in[8];
    const float* b3    = (const float*)d_in[9];

    int N = in_sizes[0];
    int E = in_sizes[1];
    int V = in_sizes[3] / 64;
    if (E > CAP_E) E = CAP_E;
    if (N > CAP_N - 2) N = CAP_N - 2;
    if (V > CAP_V) V = CAP_V;

    int nbA = (V + 127) / 128;
    int nbB = (N + 127) / 128;
    pre_kernel<<<nbA + nbB, 128>>>(nodes, u2e, w1, b1, V, N, nbA);

    int ntiles = (E + 15) / 16;
    int grid = 296;
    int maxgrid = (ntiles + 7) / 8;
    if (grid > maxgrid) grid = maxgrid;
    edge_mma_kernel<<<grid, 256>>>(neigh, seg, w2, b2, w3, b3, E, ntiles);

    agg_kernel<<<(N * 32 + 255) / 256, 256>>>(neigh, seg, u2e, (float*)d_out, N, E);
}

// round 6
// speedup vs baseline: 8.8149x; 1.3961x over previous
#include <cuda_runtime.h>
#include <cuda_bf16.h>
#include <cstdint>
#include <math.h>

#define CAP_E 655360
#define CAP_N 20004
#define CAP_V 100352

// Scratch (allocation-free rule: __device__ globals)
// preA/preB stored as packed bf16x2: 32 uint32 per row (64 cols)
__device__ uint32_t g_preA[(size_t)CAP_V * 32];
__device__ uint32_t g_preB[(size_t)CAP_N * 32];
__device__ float g_logits[CAP_E];
__device__ float g_ex[CAP_E];

// lower half <- lo, upper half <- hi
__device__ __forceinline__ uint32_t pack_bf2(float lo, float hi) {
    uint32_t r;
    asm("cvt.rn.bf16x2.f32 %0, %1, %2;" : "=r"(r) : "f"(hi), "f"(lo));
    return r;
}
__device__ __forceinline__ uint32_t cvt2(float2 v) { return pack_bf2(v.x, v.y); }
// bf16x2: relu(a + b)
__device__ __forceinline__ uint32_t hadd_relu2(uint32_t a, uint32_t b) {
    __nv_bfloat162 av = *reinterpret_cast<__nv_bfloat162*>(&a);
    __nv_bfloat162 bv = *reinterpret_cast<__nv_bfloat162*>(&b);
    __nv_bfloat162 z = __float2bfloat162_rn(0.0f);
    __nv_bfloat162 r = __hmax2(__hadd2(av, bv), z);
    return *reinterpret_cast<uint32_t*>(&r);
}
__device__ __forceinline__ void mma_16816(float* c, uint32_t a0, uint32_t a1,
                                          uint32_t a2, uint32_t a3,
                                          uint32_t b0, uint32_t b1) {
    asm volatile(
        "mma.sync.aligned.m16n8k16.row.col.f32.bf16.bf16.f32 "
        "{%0,%1,%2,%3}, {%4,%5,%6,%7}, {%8,%9}, {%0,%1,%2,%3};"
        : "+f"(c[0]), "+f"(c[1]), "+f"(c[2]), "+f"(c[3])
        : "r"(a0), "r"(a1), "r"(a2), "r"(a3), "r"(b0), "r"(b1));
}

// ---------------------------------------------------------------------------
// Kernel 1 (HMMA): pre-compute
//   preA[v] = u2e[v] @ W1[0:64]  + b1   (v in [0,V))
//   preB[n] = u2e[nodes[n]] @ W1[64:128] (n in [0,N))
// Persistent warps statically partitioned A-kind / B-kind by tile share.
// Warp-tile: 16 rows x 64 cols, K=64 -> 32 mma.sync. Output packed bf16x2.
// ---------------------------------------------------------------------------
__global__ __launch_bounds__(256) void pre_mma_kernel(
    const int* __restrict__ nodes, const float* __restrict__ u2e,
    const float* __restrict__ w1, const float* __restrict__ b1,
    int V, int N)
{
    __shared__ float s_w1[8192];   // full W1 [128][64] (32 KB)
    __shared__ float s_b1[64];

    const int tid  = threadIdx.x;
    const int lane = tid & 31;
    const int wid  = tid >> 5;
    const int g    = lane >> 2;
    const int tig  = lane & 3;

    const float4* w1v = (const float4*)w1;
    for (int i = tid; i < 2048; i += 256) ((float4*)s_w1)[i] = w1v[i];
    if (tid < 64) s_b1[tid] = b1[tid];
    __syncthreads();

    const int tA = (V + 15) / 16;
    const int tB = (N + 15) / 16;
    const int nw = gridDim.x * 8;
    const int w  = blockIdx.x * 8 + wid;
    int wA = (int)(((long long)nw * tA) / (tA + tB));
    if (wA < 1) wA = 1;
    if (wA > nw - 1) wA = nw - 1;

    const bool isA   = (w < wA);
    const int tiles  = isA ? tA : tB;
    const int tfirst = isA ? w : (w - wA);
    const int tstep  = isA ? wA : (nw - wA);
    const int rows   = isA ? V : N;
    const float* wb  = s_w1 + (isA ? 0 : 64 * 64);
    uint32_t* gout   = isA ? g_preA : g_preB;

    // B fragments from W1 half (col-major n): 64 regs
    uint32_t Bf[4][8][2];
    #pragma unroll
    for (int kc = 0; kc < 4; kc++) {
        int k0 = kc * 16 + 2 * tig;
        #pragma unroll
        for (int nc = 0; nc < 8; nc++) {
            int n = nc * 8 + g;
            Bf[kc][nc][0] = pack_bf2(wb[k0 * 64 + n],       wb[(k0 + 1) * 64 + n]);
            Bf[kc][nc][1] = pack_bf2(wb[(k0 + 8) * 64 + n], wb[(k0 + 9) * 64 + n]);
        }
    }

    for (int t = tfirst; t < tiles; t += tstep) {
        const int r0 = t * 16 + g;
        const int r1 = r0 + 8;
        const int rr0 = r0 < rows ? r0 : rows - 1;
        const int rr1 = r1 < rows ? r1 : rows - 1;
        const int src0 = isA ? rr0 : nodes[rr0];
        const int src1 = isA ? rr1 : nodes[rr1];
        const float2* x0 = (const float2*)(u2e + (size_t)src0 * 64);
        const float2* x1 = (const float2*)(u2e + (size_t)src1 * 64);

        float c[8][4];
        #pragma unroll
        for (int nc = 0; nc < 8; nc++) {
            c[nc][0] = 0.f; c[nc][1] = 0.f; c[nc][2] = 0.f; c[nc][3] = 0.f;
        }

        #pragma unroll
        for (int kc = 0; kc < 4; kc++) {
            const int i0 = kc * 8 + tig;
            const int i1 = i0 + 4;
            uint32_t a0 = cvt2(x0[i0]);
            uint32_t a1 = cvt2(x1[i0]);
            uint32_t a2 = cvt2(x0[i1]);
            uint32_t a3 = cvt2(x1[i1]);
            #pragma unroll
            for (int nc = 0; nc < 8; nc++)
                mma_16816(c[nc], a0, a1, a2, a3, Bf[kc][nc][0], Bf[kc][nc][1]);
        }

        // epilogue: add b1 (A-kind only), pack bf16x2, store
        #pragma unroll
        for (int nc = 0; nc < 8; nc++) {
            const int col0 = nc * 8 + 2 * tig;
            const float add0 = isA ? s_b1[col0] : 0.0f;
            const float add1 = isA ? s_b1[col0 + 1] : 0.0f;
            uint32_t p0 = pack_bf2(c[nc][0] + add0, c[nc][1] + add1);
            uint32_t p1 = pack_bf2(c[nc][2] + add0, c[nc][3] + add1);
            if (r0 < rows) gout[(size_t)r0 * 32 + nc * 4 + tig] = p0;
            if (r1 < rows) gout[(size_t)r1 * 32 + nc * 4 + tig] = p1;
        }
    }
}

// ---------------------------------------------------------------------------
// Kernel 2 (mma.sync): per warp-tile of 16 edges:
//   A[16,64] = relu(preA_bf[neigh] + preB_bf[seg])   (bf16x2 loads, 2 HALU ops)
//   H2 = A @ W2_bf16  via m16n8k16 HMMA, fp32 accum
//   logit[e] = b3 + sum_j relu(H2[e][j] + b2[j]) * w3[j]
// ---------------------------------------------------------------------------
__global__ __launch_bounds__(256) void edge_mma_kernel(
    const int* __restrict__ neigh, const int* __restrict__ seg,
    const float* __restrict__ w2, const float* __restrict__ b2,
    const float* __restrict__ w3, const float* __restrict__ b3,
    int E, int ntiles)
{
    __shared__ float s_w2[4096];
    __shared__ float s_b2[64];
    __shared__ float s_w3[64];
    __shared__ float s_b3;

    const int tid  = threadIdx.x;
    const int lane = tid & 31;
    const int wid  = tid >> 5;
    const int g    = lane >> 2;
    const int tig  = lane & 3;

    const float4* w2v = (const float4*)w2;
    for (int i = tid; i < 1024; i += 256) ((float4*)s_w2)[i] = w2v[i];
    if (tid < 64) { s_b2[tid] = b2[tid]; s_w3[tid] = w3[tid]; }
    if (tid == 255) s_b3 = b3[0];
    __syncthreads();

    uint32_t Bf[4][8][2];
    #pragma unroll
    for (int kc = 0; kc < 4; kc++) {
        int k0 = kc * 16 + 2 * tig;
        #pragma unroll
        for (int nc = 0; nc < 8; nc++) {
            int n = nc * 8 + g;
            Bf[kc][nc][0] = pack_bf2(s_w2[k0 * 64 + n],       s_w2[(k0 + 1) * 64 + n]);
            Bf[kc][nc][1] = pack_bf2(s_w2[(k0 + 8) * 64 + n], s_w2[(k0 + 9) * 64 + n]);
        }
    }
    const float vb3 = s_b3;

    const int warp_gid = blockIdx.x * 8 + wid;
    const int nwarps   = gridDim.x * 8;

    for (int tile = warp_gid; tile < ntiles; tile += nwarps) {
        const int base = tile * 16;
        const int e0 = base + g;
        const int e1 = e0 + 8;
        const int ee0 = e0 < E ? e0 : E - 1;
        const int ee1 = e1 < E ? e1 : E - 1;

        const uint32_t* pa0 = g_preA + (size_t)neigh[ee0] * 32;
        const uint32_t* pb0 = g_preB + (size_t)seg[ee0] * 32;
        const uint32_t* pa1 = g_preA + (size_t)neigh[ee1] * 32;
        const uint32_t* pb1 = g_preB + (size_t)seg[ee1] * 32;

        float c[8][4];
        #pragma unroll
        for (int nc = 0; nc < 8; nc++) {
            c[nc][0] = 0.f; c[nc][1] = 0.f; c[nc][2] = 0.f; c[nc][3] = 0.f;
        }

        #pragma unroll
        for (int kc = 0; kc < 4; kc++) {
            const int i0 = kc * 8 + tig;
            const int i1 = i0 + 4;
            uint32_t a0 = hadd_relu2(pa0[i0], pb0[i0]);
            uint32_t a1 = hadd_relu2(pa1[i0], pb1[i0]);
            uint32_t a2 = hadd_relu2(pa0[i1], pb0[i1]);
            uint32_t a3 = hadd_relu2(pa1[i1], pb1[i1]);

            #pragma unroll
            for (int nc = 0; nc < 8; nc++)
                mma_16816(c[nc], a0, a1, a2, a3, Bf[kc][nc][0], Bf[kc][nc][1]);
        }

        float p0 = 0.f, p1 = 0.f;
        #pragma unroll
        for (int nc = 0; nc < 8; nc++) {
            const int col0 = nc * 8 + 2 * tig;
            const int col1 = col0 + 1;
            const float bb0 = s_b2[col0], bb1 = s_b2[col1];
            const float ww0 = s_w3[col0], ww1 = s_w3[col1];
            p0 = fmaf(fmaxf(c[nc][0] + bb0, 0.f), ww0, p0);
            p0 = fmaf(fmaxf(c[nc][1] + bb1, 0.f), ww1, p0);
            p1 = fmaf(fmaxf(c[nc][2] + bb0, 0.f), ww0, p1);
            p1 = fmaf(fmaxf(c[nc][3] + bb1, 0.f), ww1, p1);
        }
        p0 += __shfl_xor_sync(0xffffffffu, p0, 1);
        p0 += __shfl_xor_sync(0xffffffffu, p0, 2);
        p1 += __shfl_xor_sync(0xffffffffu, p1, 1);
        p1 += __shfl_xor_sync(0xffffffffu, p1, 2);

        if (tig == 0) {
            if (e0 < E) g_logits[e0] = p0 + vb3;
            if (e1 < E) g_logits[e1] = p1 + vb3;
        }
    }
}

// ---------------------------------------------------------------------------
// Kernel 3: warp-per-node segment softmax + attention-weighted sum.
// ---------------------------------------------------------------------------
__global__ void agg_kernel(const int* __restrict__ neigh,
                           const int* __restrict__ seg,
                           const float* __restrict__ u2e,
                           float* __restrict__ out, int N, int E)
{
    int gw   = (blockIdx.x * blockDim.x + threadIdx.x) >> 5;
    int lane = threadIdx.x & 31;
    if (gw >= N) return;

    int bound = E;
    if (lane < 2) {
        int target = gw + lane;
        int lo = 0, hi = E;
        while (lo < hi) {
            int mid = (lo + hi) >> 1;
            if (seg[mid] < target) lo = mid + 1; else hi = mid;
        }
        bound = lo;
    }
    int s    = __shfl_sync(0xffffffffu, bound, 0);
    int epos = __shfl_sync(0xffffffffu, bound, 1);

    float m = -INFINITY;
    for (int i = s + lane; i < epos; i += 32) m = fmaxf(m, g_logits[i]);
    #pragma unroll
    for (int o = 16; o; o >>= 1) m = fmaxf(m, __shfl_xor_sync(0xffffffffu, m, o));
    if (!isfinite(m)) m = 0.0f;

    float sum = 0.0f;
    for (int i = s + lane; i < epos; i += 32) {
        float ex = __expf(g_logits[i] - m);
        g_ex[i] = ex;
        sum += ex;
    }
    #pragma unroll
    for (int o = 16; o; o >>= 1) sum += __shfl_xor_sync(0xffffffffu, sum, o);
    float inv = 1.0f / fmaxf(sum, 1e-9f);
    __syncwarp();

    // pass 3: unrolled x4 with independent accumulators (gather-latency bound)
    float ax[4] = {0.f, 0.f, 0.f, 0.f};
    float ay[4] = {0.f, 0.f, 0.f, 0.f};
    int i = s;
    for (; i + 3 < epos; i += 4) {
        float att[4];
        float2 v[4];
        #pragma unroll
        for (int u = 0; u < 4; u++) {
            att[u] = g_ex[i + u] * inv;
            v[u] = ((const float2*)(u2e + (size_t)neigh[i + u] * 64))[lane];
        }
        #pragma unroll
        for (int u = 0; u < 4; u++) {
            ax[u] = fmaf(att[u], v[u].x, ax[u]);
            ay[u] = fmaf(att[u], v[u].y, ay[u]);
        }
    }
    for (; i < epos; i++) {
        float att = g_ex[i] * inv;
        float2 v = ((const float2*)(u2e + (size_t)neigh[i] * 64))[lane];
        ax[0] = fmaf(att, v.x, ax[0]);
        ay[0] = fmaf(att, v.y, ay[0]);
    }
    float ox = (ax[0] + ax[1]) + (ax[2] + ax[3]);
    float oy = (ay[0] + ay[1]) + (ay[2] + ay[3]);
    ((float2*)out)[(size_t)gw * 32 + lane] = make_float2(ox, oy);
}

// ---------------------------------------------------------------------------
extern "C" void kernel_launch(void* const* d_in, const int* in_sizes, int n_in,
                              void* d_out, int out_size)
{
    const int*   nodes = (const int*)d_in[0];
    const int*   neigh = (const int*)d_in[1];
    const int*   seg   = (const int*)d_in[2];
    const float* u2e   = (const float*)d_in[3];
    const float* w1    = (const float*)d_in[4];
    const float* b1    = (const float*)d_in[5];
    const float* w2    = (const float*)d_in[6];
    const float* b2    = (const float*)d_in[7];
    const float* w3    = (const float*)d_in[8];
    const float* b3    = (const float*)d_in[9];

    int N = in_sizes[0];
    int E = in_sizes[1];
    int V = in_sizes[3] / 64;
    if (E > CAP_E) E = CAP_E;
    if (N > CAP_N - 2) N = CAP_N - 2;
    if (V > CAP_V) V = CAP_V;

    int pre_tiles = (V + 15) / 16 + (N + 15) / 16;
    int pre_grid = (pre_tiles + 7) / 8;
    if (pre_grid > 296) pre_grid = 296;
    pre_mma_kernel<<<pre_grid, 256>>>(nodes, u2e, w1, b1, V, N);

    int ntiles = (E + 15) / 16;
    int grid = 296;
    int maxgrid = (ntiles + 7) / 8;
    if (grid > maxgrid) grid = maxgrid;
    edge_mma_kernel<<<grid, 256>>>(neigh, seg, w2, b2, w3, b3, E, ntiles);

    agg_kernel<<<(N * 32 + 255) / 256, 256>>>(neigh, seg, u2e, (float*)d_out, N, E);
}